// round 1
// baseline (speedup 1.0000x reference)
#include <cuda_runtime.h>

// Problem constants
#define B_    2
#define S_    1024
#define HQ_   32
#define HKV_  8
#define D_    128
#define GRP_  4
#define BQ    64
#define BK    64
#define SSTR  65
#define NT    256

// -------------------------------------------------------------------------
// KV-cache scatter:  kv_out[idx[i]][h][d] = (h<8 ? xk : xv)[i][h%8][d]
// (kv_out pre-filled with kv_buffer via memcpyAsync; idx here is a
//  permutation but we implement the general scatter.)
// -------------------------------------------------------------------------
__global__ void kv_scatter_kernel(const float* __restrict__ xk,
                                  const float* __restrict__ xv,
                                  const int* __restrict__ idx,
                                  float* __restrict__ kvout) {
    int t = blockIdx.x * blockDim.x + threadIdx.x;   // float4 units
    const int total = B_ * S_ * 2 * HKV_ * (D_ / 4); // 1,048,576
    if (t >= total) return;
    int d4 = t & 31;
    int hh = (t >> 5) & 15;
    int i  = t >> 9;
    float4 v;
    if (hh < HKV_)
        v = reinterpret_cast<const float4*>(xk)[(i * HKV_ + hh) * 32 + d4];
    else
        v = reinterpret_cast<const float4*>(xv)[(i * HKV_ + (hh - HKV_)) * 32 + d4];
    int row = idx[i];
    reinterpret_cast<float4*>(kvout)[((size_t)row * 16 + hh) * 32 + d4] = v;
}

// -------------------------------------------------------------------------
// Causal GQA flash attention, fp32 FMA path.
// One CTA per (b, h, q-tile of 64). 256 threads.
//   QK phase: 16x16 thread grid, 4x4 micro-tile each.
//   PV phase: thread (q = tid>>2, seg = tid&3) owns 32 d-values
//             (chunks {seg, seg+4, ..., seg+28} — bank-quad friendly).
// K tile is XOR-swizzled per 16B chunk: phys = c ^ ((k>>2)&7) so the
// transposed-access QK loads avoid heavy bank conflicts while stores
// stay conflict-free.
// -------------------------------------------------------------------------
__global__ __launch_bounds__(NT, 1)
void attn_kernel(const float* __restrict__ xq, const float* __restrict__ xk,
                 const float* __restrict__ xv, float* __restrict__ out) {
    const int qt = (S_ / BQ - 1) - blockIdx.x;  // big tiles first (load balance)
    const int h  = blockIdx.y;
    const int b  = blockIdx.z;
    const int hk = h >> 2;                      // GQA: jnp.repeat -> h/4

    extern __shared__ float sm[];
    float* Qs   = sm;                 // [BQ][128]
    float* Ks   = Qs + BQ * D_;       // [BK][128], chunk-swizzled
    float* Vs   = Ks + BK * D_;       // [BK][128]
    float* Ss   = Vs + BK * D_;       // [BQ][SSTR]
    float* mrow = Ss + BQ * SSTR;     // [BQ]
    float* lrow = mrow + BQ;          // [BQ]
    float* frow = lrow + BQ;          // [BQ]

    const int tid    = threadIdx.x;
    const int lane_q = tid >> 2;      // PV: q row
    const int seg    = tid & 3;       // PV: d segment
    const int tx = tid & 15, ty = tid >> 4;
    const int q0 = ty * 4, k0 = tx * 4;
    const int swk = tx & 7;           // K swizzle key for this thread's rows
    const float scale = 0.08838834764831845f;  // 1/sqrt(128)

    // ---- load Q tile (pre-scaled), natural layout ----
    for (int it = tid; it < BQ * (D_ / 4); it += NT) {
        int q = it >> 5, c = it & 31;
        float4 v = *reinterpret_cast<const float4*>(
            xq + ((((size_t)b * S_ + (size_t)qt * BQ + q) * HQ_ + h) * D_ + c * 4));
        v.x *= scale; v.y *= scale; v.z *= scale; v.w *= scale;
        *reinterpret_cast<float4*>(Qs + q * D_ + c * 4) = v;
    }
    if (tid < BQ) { mrow[tid] = -1e30f; lrow[tid] = 0.0f; }

    float acc[32];
#pragma unroll
    for (int i = 0; i < 32; ++i) acc[i] = 0.0f;

    for (int kt = 0; kt <= qt; ++kt) {
        __syncthreads();  // previous tile's consumers done before overwrite

        // ---- load K (swizzled) + V tile ----
        for (int it = tid; it < BK * (D_ / 4); it += NT) {
            int k = it >> 5, c = it & 31;   // per warp: k const, c = lane
            size_t g = (((size_t)b * S_ + (size_t)kt * BK + k) * HKV_ + hk) * D_ + c * 4;
            float4 kv = *reinterpret_cast<const float4*>(xk + g);
            int pc = c ^ ((k >> 2) & 7);
            *reinterpret_cast<float4*>(Ks + k * D_ + pc * 4) = kv;
            float4 vv = *reinterpret_cast<const float4*>(xv + g);
            *reinterpret_cast<float4*>(Vs + k * D_ + c * 4) = vv;
        }
        __syncthreads();

        // ---- QK: sc[4][4] = Q[q0..3] . K[k0..3] ----
        float sc[4][4];
#pragma unroll
        for (int i = 0; i < 4; ++i)
#pragma unroll
            for (int j = 0; j < 4; ++j) sc[i][j] = 0.0f;

#pragma unroll 2
        for (int c = 0; c < 32; ++c) {
            float4 qv[4], kv[4];
#pragma unroll
            for (int i = 0; i < 4; ++i)
                qv[i] = *reinterpret_cast<const float4*>(Qs + (q0 + i) * D_ + c * 4);
            const int pc4 = (c ^ swk) * 4;
#pragma unroll
            for (int j = 0; j < 4; ++j)
                kv[j] = *reinterpret_cast<const float4*>(Ks + (k0 + j) * D_ + pc4);
#pragma unroll
            for (int i = 0; i < 4; ++i)
#pragma unroll
                for (int j = 0; j < 4; ++j) {
                    sc[i][j] += qv[i].x * kv[j].x;
                    sc[i][j] += qv[i].y * kv[j].y;
                    sc[i][j] += qv[i].z * kv[j].z;
                    sc[i][j] += qv[i].w * kv[j].w;
                }
        }

        // ---- mask (diag tile only) + store scores ----
        const bool diag = (kt == qt);
#pragma unroll
        for (int i = 0; i < 4; ++i)
#pragma unroll
            for (int j = 0; j < 4; ++j) {
                float v = sc[i][j];
                if (diag && (k0 + j) > (q0 + i)) v = -1e30f;
                Ss[(q0 + i) * SSTR + (k0 + j)] = v;
            }
        __syncthreads();

        // ---- softmax pass A: row max, rescale factor (64 threads) ----
        if (tid < BQ) {
            const float* row = Ss + tid * SSTR;
            float m_old = mrow[tid];
            float mx = m_old;
#pragma unroll 8
            for (int k = 0; k < BK; ++k) mx = fmaxf(mx, row[k]);
            float f = __expf(m_old - mx);
            mrow[tid] = mx;
            lrow[tid] *= f;
            frow[tid] = f;
        }
        __syncthreads();

        // ---- pass B: exponentiate (all 256 threads) + row sums ----
        {
            float mx = mrow[lane_q];
            float* row = Ss + lane_q * SSTR + seg * 16;
            float ps = 0.0f;
#pragma unroll
            for (int j = 0; j < 16; ++j) {
                float p = __expf(row[j] - mx);
                row[j] = p;
                ps += p;
            }
            ps += __shfl_xor_sync(0xffffffffu, ps, 1);
            ps += __shfl_xor_sync(0xffffffffu, ps, 2);
            if (seg == 0) lrow[lane_q] += ps;
        }
        __syncthreads();

        // ---- rescale accumulators + PV ----
        const float f = frow[lane_q];
#pragma unroll
        for (int i = 0; i < 32; ++i) acc[i] *= f;
        const float* srow = Ss + lane_q * SSTR;
#pragma unroll 2
        for (int k = 0; k < BK; ++k) {
            float s = srow[k];
            const float* vr = Vs + k * D_;
#pragma unroll
            for (int j = 0; j < 8; ++j) {
                float4 vv = *reinterpret_cast<const float4*>(vr + (j * 4 + seg) * 4);
                acc[4 * j + 0] += s * vv.x;
                acc[4 * j + 1] += s * vv.y;
                acc[4 * j + 2] += s * vv.z;
                acc[4 * j + 3] += s * vv.w;
            }
        }
    }

    __syncthreads();  // lrow writes visible to all
    const float linv = 1.0f / lrow[lane_q];
    float* ob = out + ((((size_t)b * S_ + (size_t)qt * BQ + lane_q) * HQ_ + h) * D_);
#pragma unroll
    for (int j = 0; j < 8; ++j) {
        float4 o;
        o.x = acc[4 * j + 0] * linv;
        o.y = acc[4 * j + 1] * linv;
        o.z = acc[4 * j + 2] * linv;
        o.w = acc[4 * j + 3] * linv;
        *reinterpret_cast<float4*>(ob + (j * 4 + seg) * 4) = o;
    }
}

// -------------------------------------------------------------------------
extern "C" void kernel_launch(void* const* d_in, const int* in_sizes, int n_in,
                              void* d_out, int out_size) {
    const float* xq    = (const float*)d_in[0];
    const float* xk    = (const float*)d_in[1];
    const float* xv    = (const float*)d_in[2];
    const float* kvbuf = (const float*)d_in[3];
    const int*   idx   = (const int*)d_in[4];

    float* out   = (float*)d_out;                       // [B,S,HQ*D]
    float* kvout = out + (size_t)B_ * S_ * HQ_ * D_;    // [B*S, 2*HKV, D]

    // kv_buffer_new = kv_buffer; then scatter rows
    cudaMemcpyAsync(kvout, kvbuf, (size_t)B_ * S_ * 2 * HKV_ * D_ * sizeof(float),
                    cudaMemcpyDeviceToDevice, 0);
    const int nvec = B_ * S_ * 2 * HKV_ * (D_ / 4);
    kv_scatter_kernel<<<(nvec + 255) / 256, 256>>>(xk, xv, idx, kvout);

    const int smem_bytes =
        (3 * BQ * D_ + BQ * SSTR + 3 * BQ) * (int)sizeof(float);  // 115,712 B
    cudaFuncSetAttribute(attn_kernel,
                         cudaFuncAttributeMaxDynamicSharedMemorySize, smem_bytes);
    attn_kernel<<<dim3(S_ / BQ, HQ_, B_), NT, smem_bytes>>>(xq, xk, xv, out);
}

// round 3
// speedup vs baseline: 6.8670x; 6.8670x over previous
#include <cuda_runtime.h>
#include <cstdint>

#define B_    2
#define S_    1024
#define HQ_   32
#define HKV_  8
#define D_    128
#define BQ    128
#define BK    64
#define NT    256
// smem strides (in 4-byte words) — chosen for conflict-free fragment LDS
#define QSTR  132
#define KSTR  132
#define VSTR  136
#define PSTR  68

static __device__ __forceinline__ uint32_t f2tf(float x) {
    uint32_t u; asm("cvt.rna.tf32.f32 %0, %1;" : "=r"(u) : "f"(x)); return u;
}
static __device__ __forceinline__ void mma8(float* d, const uint32_t* a,
                                            uint32_t b0, uint32_t b1) {
    asm volatile(
        "mma.sync.aligned.m16n8k8.row.col.f32.tf32.tf32.f32 "
        "{%0,%1,%2,%3}, {%4,%5,%6,%7}, {%8,%9}, {%0,%1,%2,%3};"
        : "+f"(d[0]), "+f"(d[1]), "+f"(d[2]), "+f"(d[3])
        : "r"(a[0]), "r"(a[1]), "r"(a[2]), "r"(a[3]), "r"(b0), "r"(b1));
}

// -------------------------------------------------------------------------
// KV-cache scatter (unchanged — correct and negligible)
// -------------------------------------------------------------------------
__global__ void kv_scatter_kernel(const float* __restrict__ xk,
                                  const float* __restrict__ xv,
                                  const int* __restrict__ idx,
                                  float* __restrict__ kvout) {
    int t = blockIdx.x * blockDim.x + threadIdx.x;
    const int total = B_ * S_ * 2 * HKV_ * (D_ / 4);
    if (t >= total) return;
    int d4 = t & 31;
    int hh = (t >> 5) & 15;
    int i  = t >> 9;
    float4 v;
    if (hh < HKV_)
        v = reinterpret_cast<const float4*>(xk)[(i * HKV_ + hh) * 32 + d4];
    else
        v = reinterpret_cast<const float4*>(xv)[(i * HKV_ + (hh - HKV_)) * 32 + d4];
    int row = idx[i];
    reinterpret_cast<float4*>(kvout)[((size_t)row * 16 + hh) * 32 + d4] = v;
}

// -------------------------------------------------------------------------
// tf32 mma.sync flash attention.
// CTA = (b, h, 128-q-row tile). 8 warps; warp w owns q rows 16w..16w+15.
// Fragment map (m16n8k8): g = lane>>2, t = lane&3.
//   A: a0=[g][t] a1=[g+8][t] a2=[g][t+4] a3=[g+8][t+4]
//   B: b0=[t][g] b1=[t+4][g]   C: c0=[g][2t] c1=[g][2t+1] c2,c3=[g+8][..]
// -------------------------------------------------------------------------
__global__ __launch_bounds__(NT, 1)
void attn_mma(const float* __restrict__ xq, const float* __restrict__ xk,
              const float* __restrict__ xv, float* __restrict__ out) {
    extern __shared__ uint32_t sm[];
    uint32_t* Qs = sm;                    // [128][QSTR] tf32
    uint32_t* Ks = Qs + BQ * QSTR;        // [64][KSTR]
    uint32_t* Vs = Ks + BK * KSTR;        // [64][VSTR]
    uint32_t* Ps = Vs + BK * VSTR;        // [128][PSTR]

    const int tid = threadIdx.x, w = tid >> 5, lane = tid & 31;
    const int g = lane >> 2, t = lane & 3;
    const int qt = (S_ / BQ - 1) - blockIdx.x;   // big tiles first
    const int h = blockIdx.y, b = blockIdx.z, hk = h >> 2;
    const int m0 = w * 16;
    const float scale = 0.08838834764831845f;    // 1/sqrt(128)

    // ---- Q tile: global -> smem (scaled, tf32) ----
    for (int it = tid; it < BQ * 32; it += NT) {
        int r = it >> 5, c4 = (it & 31) << 2;
        float4 v = *reinterpret_cast<const float4*>(
            xq + ((((size_t)b * S_ + (size_t)qt * BQ + r) * HQ_ + h) * D_ + c4));
        uint32_t* p = Qs + r * QSTR + c4;
        p[0] = f2tf(v.x * scale); p[1] = f2tf(v.y * scale);
        p[2] = f2tf(v.z * scale); p[3] = f2tf(v.w * scale);
    }
    __syncthreads();

    // ---- Q fragments to registers (held for whole kernel) ----
    uint32_t qf[16][4];
#pragma unroll
    for (int kk = 0; kk < 16; ++kk) {
        const uint32_t* r0 = Qs + (m0 + g) * QSTR + kk * 8 + t;
        const uint32_t* r1 = Qs + (m0 + g + 8) * QSTR + kk * 8 + t;
        qf[kk][0] = r0[0]; qf[kk][1] = r1[0];
        qf[kk][2] = r0[4]; qf[kk][3] = r1[4];
    }

    float Oa[16][4];
#pragma unroll
    for (int n = 0; n < 16; ++n)
#pragma unroll
        for (int c = 0; c < 4; ++c) Oa[n][c] = 0.0f;

    float m0r = -1e30f, m1r = -1e30f, l0r = 0.0f, l1r = 0.0f;
    const int q0g = qt * BQ + m0 + g;     // this thread's global q rows
    const int q1g = q0g + 8;
    const int nkt = 2 * qt + 2;

    for (int kt = 0; kt < nkt; ++kt) {
        __syncthreads();   // prior tile's K/V/P consumers done

        // ---- K,V tile: global -> smem (tf32) ----
        for (int it = tid; it < BK * 32; it += NT) {
            int r = it >> 5, c4 = (it & 31) << 2;
            size_t ga = (((size_t)b * S_ + (size_t)kt * BK + r) * HKV_ + hk) * D_ + c4;
            float4 kv = *reinterpret_cast<const float4*>(xk + ga);
            uint32_t* p = Ks + r * KSTR + c4;
            p[0] = f2tf(kv.x); p[1] = f2tf(kv.y); p[2] = f2tf(kv.z); p[3] = f2tf(kv.w);
            float4 vv = *reinterpret_cast<const float4*>(xv + ga);
            uint32_t* q = Vs + r * VSTR + c4;
            q[0] = f2tf(vv.x); q[1] = f2tf(vv.y); q[2] = f2tf(vv.z); q[3] = f2tf(vv.w);
        }
        __syncthreads();

        // ---- QK^T: S(16x64) per warp ----
        float Sa[8][4];
#pragma unroll
        for (int n = 0; n < 8; ++n)
#pragma unroll
            for (int c = 0; c < 4; ++c) Sa[n][c] = 0.0f;
#pragma unroll
        for (int kk = 0; kk < 16; ++kk) {
#pragma unroll
            for (int n = 0; n < 8; ++n) {
                const uint32_t* kb = Ks + (n * 8 + g) * KSTR + kk * 8 + t;
                mma8(Sa[n], qf[kk], kb[0], kb[4]);
            }
        }

        // ---- causal mask (only last two tiles can straddle the diagonal) ----
        if (kt >= 2 * qt) {
            const int kb0 = kt * BK;
#pragma unroll
            for (int n = 0; n < 8; ++n) {
                int c = kb0 + n * 8 + 2 * t;
                if (c     > q0g) Sa[n][0] = -1e30f;
                if (c + 1 > q0g) Sa[n][1] = -1e30f;
                if (c     > q1g) Sa[n][2] = -1e30f;
                if (c + 1 > q1g) Sa[n][3] = -1e30f;
            }
        }

        // ---- online softmax (per-warp private; quad shfl reductions) ----
        float t0 = -1e30f, t1 = -1e30f;
#pragma unroll
        for (int n = 0; n < 8; ++n) {
            t0 = fmaxf(t0, fmaxf(Sa[n][0], Sa[n][1]));
            t1 = fmaxf(t1, fmaxf(Sa[n][2], Sa[n][3]));
        }
        t0 = fmaxf(t0, __shfl_xor_sync(0xffffffffu, t0, 1));
        t0 = fmaxf(t0, __shfl_xor_sync(0xffffffffu, t0, 2));
        t1 = fmaxf(t1, __shfl_xor_sync(0xffffffffu, t1, 1));
        t1 = fmaxf(t1, __shfl_xor_sync(0xffffffffu, t1, 2));
        const float M0 = fmaxf(m0r, t0), M1 = fmaxf(m1r, t1);
        const float f0 = __expf(m0r - M0), f1 = __expf(m1r - M1);
        m0r = M0; m1r = M1;

        float s0 = 0.0f, s1 = 0.0f;
#pragma unroll
        for (int n = 0; n < 8; ++n) {
            float p00 = __expf(Sa[n][0] - M0), p01 = __expf(Sa[n][1] - M0);
            float p10 = __expf(Sa[n][2] - M1), p11 = __expf(Sa[n][3] - M1);
            s0 += p00 + p01; s1 += p10 + p11;
            uint32_t* pr0 = Ps + (m0 + g) * PSTR + n * 8 + 2 * t;
            pr0[0] = f2tf(p00); pr0[1] = f2tf(p01);
            uint32_t* pr1 = Ps + (m0 + g + 8) * PSTR + n * 8 + 2 * t;
            pr1[0] = f2tf(p10); pr1[1] = f2tf(p11);
        }
        s0 += __shfl_xor_sync(0xffffffffu, s0, 1);
        s0 += __shfl_xor_sync(0xffffffffu, s0, 2);
        s1 += __shfl_xor_sync(0xffffffffu, s1, 1);
        s1 += __shfl_xor_sync(0xffffffffu, s1, 2);
        l0r = l0r * f0 + s0;
        l1r = l1r * f1 + s1;

        // ---- rescale O, then PV (A = own P rows in smem, warp-private) ----
#pragma unroll
        for (int n = 0; n < 16; ++n) {
            Oa[n][0] *= f0; Oa[n][1] *= f0; Oa[n][2] *= f1; Oa[n][3] *= f1;
        }
        __syncwarp();
#pragma unroll
        for (int kk = 0; kk < 8; ++kk) {
            uint32_t af[4];
            const uint32_t* p0 = Ps + (m0 + g) * PSTR + kk * 8 + t;
            const uint32_t* p1 = Ps + (m0 + g + 8) * PSTR + kk * 8 + t;
            af[0] = p0[0]; af[1] = p1[0]; af[2] = p0[4]; af[3] = p1[4];
#pragma unroll
            for (int n = 0; n < 16; ++n) {
                const uint32_t* vb = Vs + (kk * 8 + t) * VSTR + n * 8 + g;
                mma8(Oa[n], af, vb[0], vb[4 * VSTR]);
            }
        }
    }

    // ---- epilogue: normalize and store ----
    const float inv0 = 1.0f / l0r, inv1 = 1.0f / l1r;
    float* ob0 = out + (((size_t)b * S_ + q0g) * HQ_ + h) * D_;
    float* ob1 = out + (((size_t)b * S_ + q1g) * HQ_ + h) * D_;
#pragma unroll
    for (int n = 0; n < 16; ++n) {
        int col = n * 8 + 2 * t;
        float2 o0; o0.x = Oa[n][0] * inv0; o0.y = Oa[n][1] * inv0;
        float2 o1; o1.x = Oa[n][2] * inv1; o1.y = Oa[n][3] * inv1;
        *reinterpret_cast<float2*>(ob0 + col) = o0;
        *reinterpret_cast<float2*>(ob1 + col) = o1;
    }
}

// -------------------------------------------------------------------------
extern "C" void kernel_launch(void* const* d_in, const int* in_sizes, int n_in,
                              void* d_out, int out_size) {
    const float* xq    = (const float*)d_in[0];
    const float* xk    = (const float*)d_in[1];
    const float* xv    = (const float*)d_in[2];
    const float* kvbuf = (const float*)d_in[3];
    const int*   idx   = (const int*)d_in[4];

    float* out   = (float*)d_out;
    float* kvout = out + (size_t)B_ * S_ * HQ_ * D_;

    cudaMemcpyAsync(kvout, kvbuf, (size_t)B_ * S_ * 2 * HKV_ * D_ * sizeof(float),
                    cudaMemcpyDeviceToDevice, 0);
    const int nvec = B_ * S_ * 2 * HKV_ * (D_ / 4);
    kv_scatter_kernel<<<(nvec + 255) / 256, 256>>>(xk, xv, idx, kvout);

    const int smem_bytes =
        (BQ * QSTR + BK * KSTR + BK * VSTR + BQ * PSTR) * (int)sizeof(uint32_t); // 171,008
    cudaFuncSetAttribute(attn_mma,
                         cudaFuncAttributeMaxDynamicSharedMemorySize, smem_bytes);
    attn_mma<<<dim3(S_ / BQ, HQ_, B_), NT, smem_bytes>>>(xq, xk, xv, out);
}

// round 5
// speedup vs baseline: 7.1538x; 1.0418x over previous
#include <cuda_runtime.h>
#include <cstdint>

#define B_    2
#define S_    1024
#define HQ_   32
#define HKV_  8
#define D_    128
#define BQ    128
#define BK    128
#define NT    512
#define QSTR  132
#define KSTR  132   // K tile, aliased by P tile (barrier-separated)
#define VSTR  136

static __device__ __forceinline__ uint32_t f2tf(float x) {
    uint32_t u; asm("cvt.rna.tf32.f32 %0, %1;" : "=r"(u) : "f"(x)); return u;
}
static __device__ __forceinline__ void mma8(float* d, const uint32_t* a,
                                            uint32_t b0, uint32_t b1) {
    asm volatile(
        "mma.sync.aligned.m16n8k8.row.col.f32.tf32.tf32.f32 "
        "{%0,%1,%2,%3}, {%4,%5,%6,%7}, {%8,%9}, {%0,%1,%2,%3};"
        : "+f"(d[0]), "+f"(d[1]), "+f"(d[2]), "+f"(d[3])
        : "r"(a[0]), "r"(a[1]), "r"(a[2]), "r"(a[3]), "r"(b0), "r"(b1));
}

// -------------------------------------------------------------------------
// KV-cache scatter (unchanged — negligible)
// -------------------------------------------------------------------------
__global__ void kv_scatter_kernel(const float* __restrict__ xk,
                                  const float* __restrict__ xv,
                                  const int* __restrict__ idx,
                                  float* __restrict__ kvout) {
    int t = blockIdx.x * blockDim.x + threadIdx.x;
    const int total = B_ * S_ * 2 * HKV_ * (D_ / 4);
    if (t >= total) return;
    int d4 = t & 31;
    int hh = (t >> 5) & 15;
    int i  = t >> 9;
    float4 v;
    if (hh < HKV_)
        v = reinterpret_cast<const float4*>(xk)[(i * HKV_ + hh) * 32 + d4];
    else
        v = reinterpret_cast<const float4*>(xv)[(i * HKV_ + (hh - HKV_)) * 32 + d4];
    int row = idx[i];
    reinterpret_cast<float4*>(kvout)[((size_t)row * 16 + hh) * 32 + d4] = v;
}

// -------------------------------------------------------------------------
// Split-K tf32 flash attention with FULLY PRIVATE halves.
// 16 warps: wq=w>>1 owns q rows 16*wq..+15; wk=w&1 owns key cols wk*64..+63.
// Each warp runs an independent online-softmax chain over its key half;
// halves merge once in the epilogue (two-way flash merge). No cross-half
// traffic in the main loop.
// -------------------------------------------------------------------------
__global__ __launch_bounds__(NT, 1)
void attn_mma(const float* __restrict__ xq, const float* __restrict__ xk,
              const float* __restrict__ xv, float* __restrict__ out) {
    extern __shared__ uint32_t sm[];
    uint32_t* Qs  = sm;                        // [128][QSTR]
    uint32_t* KPs = Qs + BQ * QSTR;            // K tile, then P tile [128][KSTR]
    uint32_t* Vs  = KPs + BK * KSTR;           // [128][VSTR]
    float* mlx   = (float*)(Vs + BK * VSTR);   // [128][2]: (m1, l1) from wk=1
    float* Ored  = (float*)Qs;                 // epilogue alias over Qs [128][132]

    const int tid = threadIdx.x, w = tid >> 5, lane = tid & 31;
    const int wq = w >> 1, wk = w & 1;
    const int g = lane >> 2, t = lane & 3;
    const int qt = (S_ / BQ - 1) - blockIdx.x;   // big tiles first
    const int h = blockIdx.y, b = blockIdx.z, hk = h >> 2;
    const int m0 = wq * 16, ko = wk * 64;
    const int r0loc = m0 + g, r1loc = m0 + g + 8;
    const float scale = 0.08838834764831845f;    // 1/sqrt(128)

    // ---- Q tile: global -> smem (scaled, tf32) ----
#pragma unroll
    for (int i8 = 0; i8 < 8; ++i8) {
        int it = tid + i8 * NT;
        int r = it >> 5, c4 = (it & 31) << 2;
        float4 v = *reinterpret_cast<const float4*>(
            xq + ((((size_t)b * S_ + (size_t)qt * BQ + r) * HQ_ + h) * D_ + c4));
        uint4 u;
        u.x = f2tf(v.x * scale); u.y = f2tf(v.y * scale);
        u.z = f2tf(v.z * scale); u.w = f2tf(v.w * scale);
        *reinterpret_cast<uint4*>(Qs + r * QSTR + c4) = u;
    }

    float Oa[16][4];
#pragma unroll
    for (int n = 0; n < 16; ++n)
#pragma unroll
        for (int c = 0; c < 4; ++c) Oa[n][c] = 0.0f;
    float mr0 = -1e30f, mr1 = -1e30f, lr0 = 0.0f, lr1 = 0.0f;

    for (int kt = 0; kt <= qt; ++kt) {
        __syncthreads();   // B1: prior P/V readers done (kt=0: nothing pending)

        // ---- K,V tile: global -> smem (tf32, vectorized stores) ----
#pragma unroll
        for (int i8 = 0; i8 < 8; ++i8) {
            int it = tid + i8 * NT;
            int r = it >> 5, c4 = (it & 31) << 2;
            size_t ga = (((size_t)b * S_ + (size_t)kt * BK + r) * HKV_ + hk) * D_ + c4;
            float4 kv = *reinterpret_cast<const float4*>(xk + ga);
            uint4 uk;
            uk.x = f2tf(kv.x); uk.y = f2tf(kv.y); uk.z = f2tf(kv.z); uk.w = f2tf(kv.w);
            *reinterpret_cast<uint4*>(KPs + r * KSTR + c4) = uk;
            float4 vv = *reinterpret_cast<const float4*>(xv + ga);
            uint4 uv;
            uv.x = f2tf(vv.x); uv.y = f2tf(vv.y); uv.z = f2tf(vv.z); uv.w = f2tf(vv.w);
            *reinterpret_cast<uint4*>(Vs + r * VSTR + c4) = uv;
        }
        __syncthreads();   // B2: K/V visible

        // ---- QK^T on own key half: S(16x64) ----
        float Sa[8][4];
#pragma unroll
        for (int n = 0; n < 8; ++n)
#pragma unroll
            for (int c = 0; c < 4; ++c) Sa[n][c] = 0.0f;
#pragma unroll
        for (int kk = 0; kk < 16; ++kk) {
            uint32_t qa[4];
            const uint32_t* qp = Qs + r0loc * QSTR + kk * 8 + t;
            qa[0] = qp[0]; qa[1] = qp[8 * QSTR];
            qa[2] = qp[4]; qa[3] = qp[8 * QSTR + 4];
#pragma unroll
            for (int n = 0; n < 8; ++n) {
                const uint32_t* kb = KPs + (ko + n * 8 + g) * KSTR + kk * 8 + t;
                mma8(Sa[n], qa, kb[0], kb[4]);
            }
        }

        // ---- causal mask (diag tile only; local row/col share tile base) ----
        if (kt == qt) {
#pragma unroll
            for (int n = 0; n < 8; ++n) {
                int c = ko + n * 8 + 2 * t;
                if (c     > r0loc) Sa[n][0] = -1e30f;
                if (c + 1 > r0loc) Sa[n][1] = -1e30f;
                if (c     > r1loc) Sa[n][2] = -1e30f;
                if (c + 1 > r1loc) Sa[n][3] = -1e30f;
            }
        }

        // ---- private online softmax (quad shfl row reductions only) ----
        float t0 = -1e30f, t1 = -1e30f;
#pragma unroll
        for (int n = 0; n < 8; ++n) {
            t0 = fmaxf(t0, fmaxf(Sa[n][0], Sa[n][1]));
            t1 = fmaxf(t1, fmaxf(Sa[n][2], Sa[n][3]));
        }
        t0 = fmaxf(t0, __shfl_xor_sync(0xffffffffu, t0, 1));
        t0 = fmaxf(t0, __shfl_xor_sync(0xffffffffu, t0, 2));
        t1 = fmaxf(t1, __shfl_xor_sync(0xffffffffu, t1, 1));
        t1 = fmaxf(t1, __shfl_xor_sync(0xffffffffu, t1, 2));
        const float M0 = fmaxf(mr0, t0), M1 = fmaxf(mr1, t1);
        const float f0 = __expf(mr0 - M0), f1 = __expf(mr1 - M1);
        mr0 = M0; mr1 = M1;

        __syncthreads();   // B3: ALL warps' K reads done -> P may overwrite K

        float s0 = 0.0f, s1 = 0.0f;
#pragma unroll
        for (int n = 0; n < 8; ++n) {
            float p00 = __expf(Sa[n][0] - M0), p01 = __expf(Sa[n][1] - M0);
            float p10 = __expf(Sa[n][2] - M1), p11 = __expf(Sa[n][3] - M1);
            s0 += p00 + p01; s1 += p10 + p11;
            uint32_t* pr0 = KPs + r0loc * KSTR + ko + n * 8 + 2 * t;
            pr0[0] = f2tf(p00); pr0[1] = f2tf(p01);
            uint32_t* pr1 = KPs + r1loc * KSTR + ko + n * 8 + 2 * t;
            pr1[0] = f2tf(p10); pr1[1] = f2tf(p11);
        }
        s0 += __shfl_xor_sync(0xffffffffu, s0, 1);
        s0 += __shfl_xor_sync(0xffffffffu, s0, 2);
        s1 += __shfl_xor_sync(0xffffffffu, s1, 1);
        s1 += __shfl_xor_sync(0xffffffffu, s1, 2);
        lr0 = lr0 * f0 + s0;
        lr1 = lr1 * f1 + s1;
        __syncwarp();      // P block is warp-private: intra-warp visibility

        // ---- rescale O, PV on own key half ----
#pragma unroll
        for (int n = 0; n < 16; ++n) {
            Oa[n][0] *= f0; Oa[n][1] *= f0; Oa[n][2] *= f1; Oa[n][3] *= f1;
        }
#pragma unroll
        for (int kk = 0; kk < 8; ++kk) {
            uint32_t af[4];
            const uint32_t* p0 = KPs + r0loc * KSTR + ko + kk * 8 + t;
            const uint32_t* p1 = p0 + 8 * KSTR;
            af[0] = p0[0]; af[1] = p1[0]; af[2] = p0[4]; af[3] = p1[4];
#pragma unroll
            for (int n = 0; n < 16; ++n) {
                const uint32_t* vb = Vs + (ko + kk * 8 + t) * VSTR + n * 8 + g;
                mma8(Oa[n], af, vb[0], vb[4 * VSTR]);
            }
        }
    }

    // ---- epilogue: two-way flash merge of the private halves ----
    __syncthreads();       // main loop fully done; Qs dead -> reuse as Ored
    if (wk == 1) {
#pragma unroll
        for (int n = 0; n < 16; ++n) {
            float* o0 = Ored + r0loc * 132 + n * 8 + 2 * t;
            o0[0] = Oa[n][0]; o0[1] = Oa[n][1];
            float* o1 = Ored + r1loc * 132 + n * 8 + 2 * t;
            o1[0] = Oa[n][2]; o1[1] = Oa[n][3];
        }
        if (t == 0) {
            mlx[2 * r0loc] = mr0; mlx[2 * r0loc + 1] = lr0;
            mlx[2 * r1loc] = mr1; mlx[2 * r1loc + 1] = lr1;
        }
    }
    __syncthreads();
    if (wk == 0) {
        const float m1a = mlx[2 * r0loc], l1a = mlx[2 * r0loc + 1];
        const float m1b = mlx[2 * r1loc], l1b = mlx[2 * r1loc + 1];
        const float Ma = fmaxf(mr0, m1a), Mb = fmaxf(mr1, m1b);
        const float c0a = __expf(mr0 - Ma), c1a = __expf(m1a - Ma);
        const float c0b = __expf(mr1 - Mb), c1b = __expf(m1b - Mb);
        const float inva = 1.0f / (lr0 * c0a + l1a * c1a);
        const float invb = 1.0f / (lr1 * c0b + l1b * c1b);
        const int q0g = qt * BQ + r0loc, q1g = qt * BQ + r1loc;
        float* ob0 = out + (((size_t)b * S_ + q0g) * HQ_ + h) * D_;
        float* ob1 = out + (((size_t)b * S_ + q1g) * HQ_ + h) * D_;
#pragma unroll
        for (int n = 0; n < 16; ++n) {
            int col = n * 8 + 2 * t;
            float2 o0, o1;
            o0.x = (Oa[n][0] * c0a + Ored[r0loc * 132 + col]     * c1a) * inva;
            o0.y = (Oa[n][1] * c0a + Ored[r0loc * 132 + col + 1] * c1a) * inva;
            o1.x = (Oa[n][2] * c0b + Ored[r1loc * 132 + col]     * c1b) * invb;
            o1.y = (Oa[n][3] * c0b + Ored[r1loc * 132 + col + 1] * c1b) * invb;
            *reinterpret_cast<float2*>(ob0 + col) = o0;
            *reinterpret_cast<float2*>(ob1 + col) = o1;
        }
    }
}

// -------------------------------------------------------------------------
extern "C" void kernel_launch(void* const* d_in, const int* in_sizes, int n_in,
                              void* d_out, int out_size) {
    const float* xq    = (const float*)d_in[0];
    const float* xk    = (const float*)d_in[1];
    const float* xv    = (const float*)d_in[2];
    const float* kvbuf = (const float*)d_in[3];
    const int*   idx   = (const int*)d_in[4];

    float* out   = (float*)d_out;
    float* kvout = out + (size_t)B_ * S_ * HQ_ * D_;

    cudaMemcpyAsync(kvout, kvbuf, (size_t)B_ * S_ * 2 * HKV_ * D_ * sizeof(float),
                    cudaMemcpyDeviceToDevice, 0);
    const int nvec = B_ * S_ * 2 * HKV_ * (D_ / 4);
    kv_scatter_kernel<<<(nvec + 255) / 256, 256>>>(xk, xv, idx, kvout);

    const int smem_bytes =
        (BQ * QSTR + BK * KSTR + BK * VSTR + 256) * (int)sizeof(uint32_t); // 205,824
    cudaFuncSetAttribute(attn_mma,
                         cudaFuncAttributeMaxDynamicSharedMemorySize, smem_bytes);
    attn_mma<<<dim3(S_ / BQ, HQ_, B_), NT, smem_bytes>>>(xq, xk, xv, out);
}